// round 5
// baseline (speedup 1.0000x reference)
#include <cuda_runtime.h>
#include <cuda_bf16.h>
#include <math.h>

// feat_rgb: [B=4, C=256, IH=128, IW=512] fp32
// out:      [4, 256, BEV_H=128, BEV_W=512] fp32
#define BEV_H 128
#define BEV_W 512
#define IH    128
#define IW    512
#define NB    4
#define NC    256
#define PLANE (IH * IW)
#define CHUNK 32                   // channels per thread (8 chunks -> fine wave tail)
#define NCH   (NC / CHUNK)

#define TWO_PI_F   6.2831853071795864769f
#define PI_F       3.1415926535897932385f
#define HALF_PI_F  1.5707963267948966192f

__device__ __forceinline__ float mod2pi(float x) {
    float m = fmodf(x, TWO_PI_F);
    if (m < 0.0f) m += TWO_PI_F;
    return m;
}

__global__ void __launch_bounds__(256)
bev_project_kernel(const float* __restrict__ feat,
                   const float* __restrict__ rot,
                   const float* __restrict__ shift_u,
                   const float* __restrict__ shift_v,
                   const float* __restrict__ mpp,
                   float* __restrict__ out)
{
    int t = blockIdx.x * blockDim.x + threadIdx.x;
    // layout: [b][cc][i][j], j fastest -> warp = 32 consecutive j (critical)
    int j  = t & (BEV_W - 1);
    int i  = (t >> 9) & (BEV_H - 1);
    int cc = (t >> 16) & (NCH - 1);
    int b  = t >> 19;

    const float r  = rot[b];
    const float su = shift_u[b];
    const float sv = shift_v[b];
    const float m  = mpp[0];

    // --- coordinates (bit-identical to R1) ---
    float center_v = (float)BEV_H * 0.5f - 0.5f + sv;
    float center_u = (float)BEV_W * 0.5f - 0.5f + su;
    float dy = (float)i - center_v;
    float dx = (float)j - center_u;
    float radius = sqrtf(dy * dy + dx * dx);

    float theta = atan2f(dy, dx);
    theta = mod2pi(-HALF_PI_F + mod2pi(theta));
    theta = mod2pi(theta + r * TWO_PI_F);
    float u = theta / TWO_PI_F * (float)IW;

    float dist = radius * m;
    float phi  = atan2f(dist, -2.0f);
    float v    = phi / PI_F * (float)IH;

    float fx = floorf(u);
    float fy = floorf(v);
    float x0 = fminf(fmaxf(fx,        0.0f), (float)(IW - 1));
    float x1 = fminf(fmaxf(fx + 1.0f, 0.0f), (float)(IW - 1));
    float y0 = fminf(fmaxf(fy,        0.0f), (float)(IH - 1));
    float y1 = fminf(fmaxf(fy + 1.0f, 0.0f), (float)(IH - 1));

    float w_nw = (x1 - u) * (y1 - v);
    float w_ne = (u - x0) * (y1 - v);
    float w_sw = (x1 - u) * (v - y0);
    float w_se = (u - x0) * (v - y0);

    int ix0 = (int)x0, ix1 = (int)x1, iy0 = (int)y0, iy1 = (int)y1;
    int i00 = iy0 * IW + ix0;
    int i01 = iy0 * IW + ix1;
    int i10 = iy1 * IW + ix0;
    int i11 = iy1 * IW + ix1;

    int c0 = cc * CHUNK;
    const float* __restrict__ p = feat + (size_t)(b * NC + c0) * PLANE;
    float* __restrict__ o = out + (size_t)((b * NC + c0) * BEV_H + i) * BEV_W + j;

    // --- software-pipelined channel loop: prefetch next channel's corners ---
    float c00 = __ldg(p + i00);
    float c01 = __ldg(p + i01);
    float c10 = __ldg(p + i10);
    float c11 = __ldg(p + i11);

    #pragma unroll 1
    for (int c = 0; c < CHUNK - 1; ++c) {
        const float* pn = p + PLANE;
        float n00 = __ldg(pn + i00);
        float n01 = __ldg(pn + i01);
        float n10 = __ldg(pn + i10);
        float n11 = __ldg(pn + i11);

        float val = c00 * w_nw + c01 * w_ne + c10 * w_sw + c11 * w_se;
        *o = val;

        c00 = n00; c01 = n01; c10 = n10; c11 = n11;
        p = pn;
        o += (size_t)BEV_H * BEV_W;
    }
    *o = c00 * w_nw + c01 * w_ne + c10 * w_sw + c11 * w_se;
}

extern "C" void kernel_launch(void* const* d_in, const int* in_sizes, int n_in,
                              void* d_out, int out_size)
{
    const float* feat    = (const float*)d_in[0];
    const float* rot     = (const float*)d_in[1];
    const float* shift_u = (const float*)d_in[2];
    const float* shift_v = (const float*)d_in[3];
    const float* mpp     = (const float*)d_in[4];
    float* out = (float*)d_out;

    int total = NB * NCH * BEV_H * BEV_W;   // 4*8*128*512 = 2,097,152 threads
    int threads = 256;
    int blocks = total / threads;           // 8192
    bev_project_kernel<<<blocks, threads>>>(feat, rot, shift_u, shift_v, mpp, out);
}

// round 6
// speedup vs baseline: 1.3141x; 1.3141x over previous
#include <cuda_runtime.h>
#include <cuda_bf16.h>
#include <math.h>

// feat_rgb: [B=4, C=256, IH=128, IW=512] fp32
// out:      [4, 256, BEV_H=128, BEV_W=512] fp32
#define BEV_H 128
#define BEV_W 512
#define IH    128
#define IW    512
#define NB    4
#define NC    256
#define PLANE (IH * IW)
#define CHUNK 64                   // channels per thread (amortize coord math)
#define NCH   (NC / CHUNK)
#define UB    8                    // channel batch: 4*UB = 32 forced loads in flight

#define TWO_PI_F   6.2831853071795864769f
#define PI_F       3.1415926535897932385f
#define HALF_PI_F  1.5707963267948966192f

__device__ __forceinline__ float mod2pi(float x) {
    float m = fmodf(x, TWO_PI_F);
    if (m < 0.0f) m += TWO_PI_F;
    return m;
}

// Volatile non-coherent global load: ptxas cannot sink or coalesce-away these,
// forcing all loads of a batch to be in flight before first consumption.
__device__ __forceinline__ float ldg_forced(const float* p) {
    float v;
    asm volatile("ld.global.nc.f32 %0, [%1];" : "=f"(v) : "l"(p));
    return v;
}

__global__ void __launch_bounds__(128)
bev_project_kernel(const float* __restrict__ feat,
                   const float* __restrict__ rot,
                   const float* __restrict__ shift_u,
                   const float* __restrict__ shift_v,
                   const float* __restrict__ mpp,
                   float* __restrict__ out)
{
    int t = blockIdx.x * blockDim.x + threadIdx.x;
    // layout: [b][cc][i][j], j fastest -> warp = 32 consecutive j (critical)
    int j  = t & (BEV_W - 1);
    int i  = (t >> 9) & (BEV_H - 1);
    int cc = (t >> 16) & (NCH - 1);
    int b  = t >> 18;

    const float r  = rot[b];
    const float su = shift_u[b];
    const float sv = shift_v[b];
    const float m  = mpp[0];

    // --- coordinates (bit-identical to R1) ---
    float center_v = (float)BEV_H * 0.5f - 0.5f + sv;
    float center_u = (float)BEV_W * 0.5f - 0.5f + su;
    float dy = (float)i - center_v;
    float dx = (float)j - center_u;
    float radius = sqrtf(dy * dy + dx * dx);

    float theta = atan2f(dy, dx);
    theta = mod2pi(-HALF_PI_F + mod2pi(theta));
    theta = mod2pi(theta + r * TWO_PI_F);
    float u = theta / TWO_PI_F * (float)IW;

    float dist = radius * m;
    float phi  = atan2f(dist, -2.0f);
    float v    = phi / PI_F * (float)IH;

    float fx = floorf(u);
    float fy = floorf(v);
    float x0 = fminf(fmaxf(fx,        0.0f), (float)(IW - 1));
    float x1 = fminf(fmaxf(fx + 1.0f, 0.0f), (float)(IW - 1));
    float y0 = fminf(fmaxf(fy,        0.0f), (float)(IH - 1));
    float y1 = fminf(fmaxf(fy + 1.0f, 0.0f), (float)(IH - 1));

    float w_nw = (x1 - u) * (y1 - v);
    float w_ne = (u - x0) * (y1 - v);
    float w_sw = (x1 - u) * (v - y0);
    float w_se = (u - x0) * (v - y0);

    int ix0 = (int)x0, ix1 = (int)x1, iy0 = (int)y0, iy1 = (int)y1;
    int i00 = iy0 * IW + ix0;
    int i01 = iy0 * IW + ix1;
    int i10 = iy1 * IW + ix0;
    int i11 = iy1 * IW + ix1;

    int c0 = cc * CHUNK;
    const float* __restrict__ p = feat + (size_t)(b * NC + c0) * PLANE;
    float* __restrict__ o = out + (size_t)((b * NC + c0) * BEV_H + i) * BEV_W + j;

    // --- channel loop: UB channels per batch, 4*UB volatile loads in flight ---
    #pragma unroll 1
    for (int c = 0; c < CHUNK; c += UB) {
        float a00[UB], a01[UB], a10[UB], a11[UB];
        const float* pp = p;
        #pragma unroll
        for (int q = 0; q < UB; ++q) {
            a00[q] = ldg_forced(pp + i00);
            a01[q] = ldg_forced(pp + i01);
            a10[q] = ldg_forced(pp + i10);
            a11[q] = ldg_forced(pp + i11);
            pp += PLANE;
        }
        float* oo = o;
        #pragma unroll
        for (int q = 0; q < UB; ++q) {
            float val = a00[q] * w_nw + a01[q] * w_ne
                      + a10[q] * w_sw + a11[q] * w_se;
            *oo = val;
            oo += (size_t)BEV_H * BEV_W;
        }
        p += (size_t)UB * PLANE;
        o += (size_t)UB * BEV_H * BEV_W;
    }
}

extern "C" void kernel_launch(void* const* d_in, const int* in_sizes, int n_in,
                              void* d_out, int out_size)
{
    const float* feat    = (const float*)d_in[0];
    const float* rot     = (const float*)d_in[1];
    const float* shift_u = (const float*)d_in[2];
    const float* shift_v = (const float*)d_in[3];
    const float* mpp     = (const float*)d_in[4];
    float* out = (float*)d_out;

    int total = NB * NCH * BEV_H * BEV_W;   // 1,048,576 threads
    int threads = 128;
    int blocks = total / threads;           // 8192
    bev_project_kernel<<<blocks, threads>>>(feat, rot, shift_u, shift_v, mpp, out);
}

// round 7
// speedup vs baseline: 1.4817x; 1.1276x over previous
#include <cuda_runtime.h>
#include <cuda_bf16.h>
#include <math.h>

// feat_rgb: [B=4, C=256, IH=128, IW=512] fp32
// out:      [4, 256, BEV_H=128, BEV_W=512] fp32
#define BEV_H 128
#define BEV_W 512
#define IH    128
#define IW    512
#define NB    4
#define NC    256
#define PLANE (IH * IW)
#define NPIX  (NB * BEV_H * BEV_W)     // 262144
#define CHUNK 32                       // channels per thread in sampling kernel
#define NCH   (NC / CHUNK)             // 8

#define TWO_PI_F   6.2831853071795864769f
#define PI_F       3.1415926535897932385f
#define HALF_PI_F  1.5707963267948966192f

// Precomputed per-(b,pixel) sampling records (8.4 MB total, L2-resident)
__device__ int4   g_idx[NPIX];   // i00, i01, i10, i11
__device__ float4 g_w[NPIX];     // w_nw, w_ne, w_sw, w_se

__device__ __forceinline__ float mod2pi(float x) {
    float m = fmodf(x, TWO_PI_F);
    if (m < 0.0f) m += TWO_PI_F;
    return m;
}

// ---------------- Kernel A: coordinates -> records (once per pixel) --------
__global__ void __launch_bounds__(256)
bev_coords_kernel(const float* __restrict__ rot,
                  const float* __restrict__ shift_u,
                  const float* __restrict__ shift_v,
                  const float* __restrict__ mpp)
{
    int t = blockIdx.x * blockDim.x + threadIdx.x;   // [b][i][j], j fastest
    int j = t & (BEV_W - 1);
    int i = (t >> 9) & (BEV_H - 1);
    int b = t >> 16;

    const float r  = rot[b];
    const float su = shift_u[b];
    const float sv = shift_v[b];
    const float m  = mpp[0];

    float center_v = (float)BEV_H * 0.5f - 0.5f + sv;
    float center_u = (float)BEV_W * 0.5f - 0.5f + su;
    float dy = (float)i - center_v;
    float dx = (float)j - center_u;
    float radius = sqrtf(dy * dy + dx * dx);

    float theta = atan2f(dy, dx);
    theta = mod2pi(-HALF_PI_F + mod2pi(theta));
    theta = mod2pi(theta + r * TWO_PI_F);
    float u = theta / TWO_PI_F * (float)IW;

    float dist = radius * m;
    float phi  = atan2f(dist, -2.0f);
    float v    = phi / PI_F * (float)IH;

    float fx = floorf(u);
    float fy = floorf(v);
    float x0 = fminf(fmaxf(fx,        0.0f), (float)(IW - 1));
    float x1 = fminf(fmaxf(fx + 1.0f, 0.0f), (float)(IW - 1));
    float y0 = fminf(fmaxf(fy,        0.0f), (float)(IH - 1));
    float y1 = fminf(fmaxf(fy + 1.0f, 0.0f), (float)(IH - 1));

    float4 w;
    w.x = (x1 - u) * (y1 - v);   // w_nw
    w.y = (u - x0) * (y1 - v);   // w_ne
    w.z = (x1 - u) * (v - y0);   // w_sw
    w.w = (u - x0) * (v - y0);   // w_se

    int ix0 = (int)x0, ix1 = (int)x1, iy0 = (int)y0, iy1 = (int)y1;
    int4 idx;
    idx.x = iy0 * IW + ix0;
    idx.y = iy0 * IW + ix1;
    idx.z = iy1 * IW + ix0;
    idx.w = iy1 * IW + ix1;

    g_idx[t] = idx;
    g_w[t]   = w;
}

// ---------------- Kernel B: gather + blend (hot loop) ----------------------
__global__ void __launch_bounds__(256)
bev_sample_kernel(const float* __restrict__ feat,
                  float* __restrict__ out)
{
    int t = blockIdx.x * blockDim.x + threadIdx.x;
    // layout: [b][cc][i][j], j fastest -> warp = 32 consecutive j (critical)
    int j  = t & (BEV_W - 1);
    int i  = (t >> 9) & (BEV_H - 1);
    int cc = (t >> 16) & (NCH - 1);
    int b  = t >> 19;

    int rec = (b << 16) | (i << 9) | j;          // record index (channel-free)
    const int4   idx = g_idx[rec];
    const float4 w   = g_w[rec];

    int c0 = cc * CHUNK;
    const float* __restrict__ p = feat + (size_t)(b * NC + c0) * PLANE;
    float* __restrict__ o = out + (size_t)((b * NC + c0) * BEV_H + i) * BEV_W + j;

    #pragma unroll 4
    for (int c = 0; c < CHUNK; ++c) {
        float a00 = __ldg(p + idx.x);
        float a01 = __ldg(p + idx.y);
        float a10 = __ldg(p + idx.z);
        float a11 = __ldg(p + idx.w);
        *o = a00 * w.x + a01 * w.y + a10 * w.z + a11 * w.w;
        p += PLANE;
        o += (size_t)BEV_H * BEV_W;
    }
}

extern "C" void kernel_launch(void* const* d_in, const int* in_sizes, int n_in,
                              void* d_out, int out_size)
{
    const float* feat    = (const float*)d_in[0];
    const float* rot     = (const float*)d_in[1];
    const float* shift_u = (const float*)d_in[2];
    const float* shift_v = (const float*)d_in[3];
    const float* mpp     = (const float*)d_in[4];
    float* out = (float*)d_out;

    // Kernel A: one thread per (b, pixel)
    bev_coords_kernel<<<NPIX / 256, 256>>>(rot, shift_u, shift_v, mpp);

    // Kernel B: one thread per (b, channel-chunk, pixel)
    int total = NB * NCH * BEV_H * BEV_W;   // 2,097,152
    bev_sample_kernel<<<total / 256, 256>>>(feat, out);
}